// round 6
// baseline (speedup 1.0000x reference)
#include <cuda_runtime.h>
#include <cuda_bf16.h>
#include <math.h>
#include <stdint.h>

// Problem shape
#define BATCH 32
#define LDIM  512
#define DDIM  768
#define EPSF  1e-5f

#define TILES_D 6
#define NPAIRS  21                  // upper-triangular 128x128 tile pairs
#define BK      32                  // k per stage (one 128B row per d)
#define NCHUNK  (LDIM / BK)         // 16
#define STAGES  3
#define OP_FLOATS   (128 * BK)      // 4096 floats = 16KB per operand tile
#define STAGE_FLOATS (2 * OP_FLOATS)
#define SMEM_BYTES  (STAGES * STAGE_FLOATS * 4)   // 98304

// Scratch: transposed, weight-folded, tf32-rounded copy  Zt[b][d][l]
__device__ float g_w[BATCH * LDIM];
__device__ float g_Zt[BATCH * DDIM * LDIM];

__device__ __forceinline__ float to_tf32(float f) {
    uint32_t u;
    asm("cvt.rna.tf32.f32 %0, %1;" : "=r"(u) : "f"(f));
    return __uint_as_float(u);
}
__device__ __forceinline__ void cp16(uint32_t saddr, const void* g) {
    asm volatile("cp.async.cg.shared.global [%0], [%1], 16;" :: "r"(saddr), "l"(g));
}
__device__ __forceinline__ void ldsm4(uint32_t* r, uint32_t addr) {
    asm volatile("ldmatrix.sync.aligned.m8n8.x4.shared.b16 {%0,%1,%2,%3}, [%4];"
        : "=r"(r[0]), "=r"(r[1]), "=r"(r[2]), "=r"(r[3]) : "r"(addr));
}
__device__ __forceinline__ void mma_tf32(float* c, const uint32_t* a, uint32_t b0, uint32_t b1) {
    asm volatile(
        "mma.sync.aligned.m16n8k8.row.col.f32.tf32.tf32.f32 "
        "{%0,%1,%2,%3}, {%4,%5,%6,%7}, {%8,%9}, {%0,%1,%2,%3};"
        : "+f"(c[0]), "+f"(c[1]), "+f"(c[2]), "+f"(c[3])
        : "r"(a[0]), "r"(a[1]), "r"(a[2]), "r"(a[3]), "r"(b0), "r"(b1));
}

// ---------------------------------------------------------------------------
// Kernel 1: w[b,l] -> sqrt(sqrt(eps + ||x||^2))   (i.e. sqrt(w))
// ---------------------------------------------------------------------------
__global__ void weight_kernel(const float* __restrict__ x) {
    int row = blockIdx.x * 8 + threadIdx.y;
    const float4* p = (const float4*)(x + (size_t)row * DDIM);
    float s = 0.f;
    #pragma unroll
    for (int i = 0; i < 6; i++) {
        float4 v = p[threadIdx.x + i * 32];
        s = fmaf(v.x, v.x, s); s = fmaf(v.y, v.y, s);
        s = fmaf(v.z, v.z, s); s = fmaf(v.w, v.w, s);
    }
    #pragma unroll
    for (int o = 16; o > 0; o >>= 1) s += __shfl_xor_sync(0xffffffffu, s, o);
    if (threadIdx.x == 0) g_w[row] = sqrtf(sqrtf(EPSF + s));
}

// ---------------------------------------------------------------------------
// Kernel 2: Zt[b][d][l] = rna_tf32( sqrt(w[b,l]) * X[b][l][d] )  (tiled transpose)
// ---------------------------------------------------------------------------
__global__ void transpose_kernel(const float* __restrict__ x) {
    __shared__ float tile[32][33];
    int b  = blockIdx.z;
    int d0 = blockIdx.x * 32;
    int l0 = blockIdx.y * 32;
    const float* Xb = x + (size_t)b * LDIM * DDIM;
    float* Zb = g_Zt + (size_t)b * DDIM * LDIM;
    int tx = threadIdx.x, ty = threadIdx.y;

    #pragma unroll
    for (int i = 0; i < 4; i++) {
        int l = l0 + ty + i * 8;
        tile[ty + i * 8][tx] = to_tf32(Xb[(size_t)l * DDIM + d0 + tx] * g_w[b * LDIM + l]);
    }
    __syncthreads();
    #pragma unroll
    for (int i = 0; i < 4; i++) {
        int d = d0 + ty + i * 8;
        Zb[(size_t)d * LDIM + l0 + tx] = tile[tx][ty + i * 8];
    }
}

// ---------------------------------------------------------------------------
// Kernel 3: C tile = Zt_m Zt_n^T via tf32 mma.sync + ldmatrix + cp.async.
// Smem operand tile: 128 rows(d) x 32 floats(k), 16B units XOR-swizzled by row.
// ---------------------------------------------------------------------------
extern __shared__ float smf[];

__global__ __launch_bounds__(256, 2)
void gram_tc_kernel(float* __restrict__ C) {
    int p = blockIdx.x % NPAIRS;
    int b = blockIdx.x / NPAIRS;
    int ti = 0, rem = p;
    while (rem >= TILES_D - ti) { rem -= TILES_D - ti; ti++; }
    int tj = ti + rem;
    int m0 = ti * 128, n0 = tj * 128;

    const float* __restrict__ Zb = g_Zt + (size_t)b * DDIM * LDIM;
    float* __restrict__ Cb = C + (size_t)b * DDIM * DDIM;

    int tid  = threadIdx.x;
    int wid  = tid >> 5, lane = tid & 31;
    int g = lane >> 2, t = lane & 3;
    int wm = (wid & 1) * 64;
    int wn = (wid >> 1) * 32;

    uint32_t sbase = (uint32_t)__cvta_generic_to_shared(smf);

    // cp.async slots: 1024 16B chunks per operand; 4 per thread per operand.
    // slot j: row = j>>3 (0..127), u = j&7 (16B unit within 128B row)
    int goff[4];      // float offset into Zb row-space (without m0/n0 row base)
    int sdst[4];      // swizzled smem float offset
    #pragma unroll
    for (int i = 0; i < 4; i++) {
        int j = tid + i * 256;
        int row = j >> 3, u = j & 7;
        goff[i] = row * LDIM + u * 4;
        sdst[i] = row * BK + ((u ^ (row & 7)) * 4);
    }

    auto ISSUE = [&](int chunk) {
        uint32_t base = sbase + (chunk % STAGES) * (STAGE_FLOATS * 4);
        int kc = chunk * BK;
        #pragma unroll
        for (int i = 0; i < 4; i++) {
            cp16(base + sdst[i] * 4,
                 Zb + (size_t)m0 * LDIM + kc + goff[i]);
            cp16(base + (OP_FLOATS + sdst[i]) * 4,
                 Zb + (size_t)n0 * LDIM + kc + goff[i]);
        }
    };

    // ldmatrix row/row7 precompute
    int rowA[4], r7A[4];
    #pragma unroll
    for (int i = 0; i < 4; i++) {
        rowA[i] = wm + 16 * i + (lane & 7) + 8 * ((lane >> 3) & 1);
        r7A[i]  = rowA[i] & 7;
    }
    int uselA = lane >> 4;             // 0/1 -> k half
    int rowB[2], r7B[2];
    #pragma unroll
    for (int jp = 0; jp < 2; jp++) {
        rowB[jp] = wn + 16 * jp + (lane & 7) + 8 * (lane >> 4);
        r7B[jp]  = rowB[jp] & 7;
    }
    int uselB = (lane >> 3) & 1;

    // Prologue
    #pragma unroll
    for (int c = 0; c < STAGES - 1; c++) {
        ISSUE(c);
        asm volatile("cp.async.commit_group;" ::: "memory");
    }

    float acc[4][4][4];
    #pragma unroll
    for (int i = 0; i < 4; i++)
        #pragma unroll
        for (int j = 0; j < 4; j++)
            #pragma unroll
            for (int r = 0; r < 4; r++) acc[i][j][r] = 0.f;

    for (int c = 0; c < NCHUNK; c++) {
        asm volatile("cp.async.wait_group %0;" :: "n"(STAGES - 2) : "memory");
        __syncthreads();

        uint32_t Ab = sbase + (c % STAGES) * (STAGE_FLOATS * 4);
        uint32_t Bb = Ab + OP_FLOATS * 4;

        #pragma unroll
        for (int kk = 0; kk < BK; kk += 8) {
            int ku = kk >> 2;
            uint32_t afr[4][4];
            #pragma unroll
            for (int i = 0; i < 4; i++)
                ldsm4(afr[i], Ab + rowA[i] * (BK * 4)
                               + (((ku + uselA) ^ r7A[i]) << 4));
            uint32_t bfr[2][4];
            #pragma unroll
            for (int jp = 0; jp < 2; jp++)
                ldsm4(bfr[jp], Bb + rowB[jp] * (BK * 4)
                                + (((ku + uselB) ^ r7B[jp]) << 4));
            #pragma unroll
            for (int i = 0; i < 4; i++)
                #pragma unroll
                for (int j = 0; j < 4; j++)
                    mma_tf32(acc[i][j], afr[i],
                             bfr[j >> 1][(j & 1) * 2], bfr[j >> 1][(j & 1) * 2 + 1]);
        }

        if (c + STAGES - 1 < NCHUNK) ISSUE(c + STAGES - 1);
        asm volatile("cp.async.commit_group;" ::: "memory");
    }

    // Epilogue: direct tile
    #pragma unroll
    for (int i = 0; i < 4; i++) {
        #pragma unroll
        for (int j = 0; j < 4; j++) {
            int m = m0 + wm + 16 * i + g;
            int n = n0 + wn + 8 * j + 2 * t;
            *(float2*)(Cb + (size_t)m * DDIM + n) =
                make_float2(acc[i][j][0], acc[i][j][1]);
            *(float2*)(Cb + (size_t)(m + 8) * DDIM + n) =
                make_float2(acc[i][j][2], acc[i][j][3]);
        }
    }
    // Mirror for off-diagonal tile pairs
    if (ti != tj) {
        #pragma unroll
        for (int i = 0; i < 4; i++) {
            #pragma unroll
            for (int j = 0; j < 4; j++) {
                int m = m0 + wm + 16 * i + g;
                int n = n0 + wn + 8 * j + 2 * t;
                Cb[(size_t)n * DDIM + m]           = acc[i][j][0];
                Cb[(size_t)(n + 1) * DDIM + m]     = acc[i][j][1];
                Cb[(size_t)n * DDIM + m + 8]       = acc[i][j][2];
                Cb[(size_t)(n + 1) * DDIM + m + 8] = acc[i][j][3];
            }
        }
    }
}

// ---------------------------------------------------------------------------
extern "C" void kernel_launch(void* const* d_in, const int* in_sizes, int n_in,
                              void* d_out, int out_size) {
    const float* x = (const float*)d_in[0];
    float* out = (float*)d_out;

    static int configured = 0;
    if (!configured) {
        cudaFuncSetAttribute(gram_tc_kernel,
                             cudaFuncAttributeMaxDynamicSharedMemorySize, SMEM_BYTES);
        configured = 1;
    }

    weight_kernel<<<(BATCH * LDIM) / 8, dim3(32, 8)>>>(x);
    transpose_kernel<<<dim3(DDIM / 32, LDIM / 32, BATCH), dim3(32, 8)>>>(x);
    gram_tc_kernel<<<BATCH * NPAIRS, 256, SMEM_BYTES>>>(out);
}

// round 7
// speedup vs baseline: 1.0330x; 1.0330x over previous
#include <cuda_runtime.h>
#include <cuda_bf16.h>
#include <math.h>
#include <stdint.h>

// Problem shape
#define BATCH 32
#define LDIM  512
#define DDIM  768
#define EPSF  1e-5f

#define TILES_D 6
#define NPAIRS  21                  // upper-triangular 128x128 tile pairs
#define BK      32                  // k per stage
#define NCHUNK  (LDIM / BK)         // 16
#define STAGES  3
#define OP_FLOATS   (128 * BK)      // 4096 floats = 16KB per operand tile
#define STAGE_FLOATS (2 * OP_FLOATS)
#define SMEM_BYTES  (STAGES * STAGE_FLOATS * 4)   // 98304

// Prep smem: 32 rows x 769 floats (pad -> conflict-free transpose) + 32 w's
#define PPAD 769
#define PREP_SMEM ((32 * PPAD + 32) * 4)          // 98560

// Scratch: transposed, weight-folded, tf32-rounded copy  Zt[b][d][l]
__device__ float g_Zt[BATCH * DDIM * LDIM];

__device__ __forceinline__ float to_tf32(float f) {
    uint32_t u;
    asm("cvt.rna.tf32.f32 %0, %1;" : "=r"(u) : "f"(f));
    return __uint_as_float(u);
}
__device__ __forceinline__ void cp16(uint32_t saddr, const void* g) {
    asm volatile("cp.async.cg.shared.global [%0], [%1], 16;" :: "r"(saddr), "l"(g));
}
__device__ __forceinline__ void ldsm4(uint32_t* r, uint32_t addr) {
    asm volatile("ldmatrix.sync.aligned.m8n8.x4.shared.b16 {%0,%1,%2,%3}, [%4];"
        : "=r"(r[0]), "=r"(r[1]), "=r"(r[2]), "=r"(r[3]) : "r"(addr));
}
__device__ __forceinline__ void mma_tf32(float* c, const uint32_t* a, uint32_t b0, uint32_t b1) {
    asm volatile(
        "mma.sync.aligned.m16n8k8.row.col.f32.tf32.tf32.f32 "
        "{%0,%1,%2,%3}, {%4,%5,%6,%7}, {%8,%9}, {%0,%1,%2,%3};"
        : "+f"(c[0]), "+f"(c[1]), "+f"(c[2]), "+f"(c[3])
        : "r"(a[0]), "r"(a[1]), "r"(a[2]), "r"(a[3]), "r"(b0), "r"(b1));
}

// ---------------------------------------------------------------------------
// Kernel 1 (fused prep): one pass over X.
// Per CTA: stage 32 token rows in smem, compute w per row, write
// Zt[b][d][l0..l0+31] = rna_tf32( sqrt(w[l]) * X[b][l][d] ), transposed.
// ---------------------------------------------------------------------------
extern __shared__ float psh[];

__global__ __launch_bounds__(256, 2)
void prep_kernel(const float* __restrict__ x) {
    float* wbuf = psh + 32 * PPAD;
    int b  = blockIdx.y;
    int l0 = blockIdx.x * 32;
    const float* __restrict__ Xb = x + ((size_t)b * LDIM + l0) * DDIM;
    int tid = threadIdx.x;
    int wid = tid >> 5, lane = tid & 31;

    // Load 32x768 floats (coalesced float4), scalar STS into padded rows
    #pragma unroll
    for (int i = 0; i < 24; i++) {
        int idx = tid + i * 256;            // 0..6143 float4 slots
        int row = idx / 192, c4 = idx % 192;
        float4 v = *(const float4*)(Xb + (size_t)row * DDIM + c4 * 4);
        float* d = psh + row * PPAD + c4 * 4;
        d[0] = v.x; d[1] = v.y; d[2] = v.z; d[3] = v.w;
    }
    __syncthreads();

    // Per-row sum of squares: warp wid handles rows 4*wid..4*wid+3
    #pragma unroll
    for (int r4 = 0; r4 < 4; r4++) {
        int r = wid * 4 + r4;
        const float* row = psh + r * PPAD;
        float s = 0.f;
        #pragma unroll
        for (int i = 0; i < 24; i++) {
            float v = row[lane + i * 32];
            s = fmaf(v, v, s);
        }
        #pragma unroll
        for (int o = 16; o > 0; o >>= 1) s += __shfl_xor_sync(0xffffffffu, s, o);
        if (lane == 0) wbuf[r] = sqrtf(sqrtf(EPSF + s));   // sqrt(w)
    }
    __syncthreads();

    // Transposed write: lane covers l-pair (li2, li2+1); halves cover 2 d rows
    int half = lane >> 4;
    int li2  = (lane & 15) * 2;
    float sw0 = wbuf[li2], sw1 = wbuf[li2 + 1];
    float* __restrict__ Zb = g_Zt + (size_t)b * DDIM * LDIM + l0;

    #pragma unroll 4
    for (int it = 0; it < 48; it++) {
        int dd = wid + 8 * (2 * it + half);            // 0..767, disjoint cover
        float v0 = psh[li2 * PPAD + dd] * sw0;
        float v1 = psh[(li2 + 1) * PPAD + dd] * sw1;
        float2 o2 = make_float2(to_tf32(v0), to_tf32(v1));
        *(float2*)(Zb + (size_t)dd * LDIM + li2) = o2;
    }
}

// ---------------------------------------------------------------------------
// Kernel 2: C tile = Zt_m Zt_n^T via tf32 mma.sync + ldmatrix + cp.async.
// Smem operand tile: 128 rows(d) x 32 floats(k), 16B units XOR-swizzled by row.
// ---------------------------------------------------------------------------
extern __shared__ float smf[];

__global__ __launch_bounds__(256, 2)
void gram_tc_kernel(float* __restrict__ C) {
    int p = blockIdx.x % NPAIRS;
    int b = blockIdx.x / NPAIRS;
    int ti = 0, rem = p;
    while (rem >= TILES_D - ti) { rem -= TILES_D - ti; ti++; }
    int tj = ti + rem;
    int m0 = ti * 128, n0 = tj * 128;

    const float* __restrict__ Zb = g_Zt + (size_t)b * DDIM * LDIM;
    float* __restrict__ Cb = C + (size_t)b * DDIM * DDIM;

    int tid  = threadIdx.x;
    int wid  = tid >> 5, lane = tid & 31;
    int g = lane >> 2, t = lane & 3;
    int wm = (wid & 1) * 64;
    int wn = (wid >> 1) * 32;

    uint32_t sbase = (uint32_t)__cvta_generic_to_shared(smf);

    // cp.async slots: 1024 16B chunks per operand; 4 per thread per operand.
    const float* gAr[4]; const float* gBr[4]; int sdst[4];
    #pragma unroll
    for (int i = 0; i < 4; i++) {
        int j = tid + i * 256;
        int row = j >> 3, u = j & 7;
        gAr[i] = Zb + (size_t)(m0 + row) * LDIM + u * 4;
        gBr[i] = Zb + (size_t)(n0 + row) * LDIM + u * 4;
        sdst[i] = (row * BK + ((u ^ (row & 7)) * 4)) * 4;   // byte offset
    }

    auto ISSUE = [&](int chunk) {
        uint32_t base = sbase + (chunk % STAGES) * (STAGE_FLOATS * 4);
        int kc = chunk * BK;
        #pragma unroll
        for (int i = 0; i < 4; i++) {
            cp16(base + sdst[i],                   gAr[i] + kc);
            cp16(base + OP_FLOATS * 4 + sdst[i],   gBr[i] + kc);
        }
    };

    // ldmatrix row precompute
    int rowA[4], r7A[4];
    #pragma unroll
    for (int i = 0; i < 4; i++) {
        rowA[i] = wm + 16 * i + (lane & 7) + 8 * ((lane >> 3) & 1);
        r7A[i]  = rowA[i] & 7;
    }
    int uselA = lane >> 4;
    int rowB[2], r7B[2];
    #pragma unroll
    for (int jp = 0; jp < 2; jp++) {
        rowB[jp] = wn + 16 * jp + (lane & 7) + 8 * (lane >> 4);
        r7B[jp]  = rowB[jp] & 7;
    }
    int uselB = (lane >> 3) & 1;

    // Prologue
    #pragma unroll
    for (int c = 0; c < STAGES - 1; c++) {
        ISSUE(c);
        asm volatile("cp.async.commit_group;" ::: "memory");
    }

    float acc[4][4][4];
    #pragma unroll
    for (int i = 0; i < 4; i++)
        #pragma unroll
        for (int j = 0; j < 4; j++)
            #pragma unroll
            for (int r = 0; r < 4; r++) acc[i][j][r] = 0.f;

    for (int c = 0; c < NCHUNK; c++) {
        asm volatile("cp.async.wait_group %0;" :: "n"(STAGES - 2) : "memory");
        __syncthreads();

        // Issue next-stage loads FIRST so they overlap the MMA block below.
        if (c + STAGES - 1 < NCHUNK) ISSUE(c + STAGES - 1);
        asm volatile("cp.async.commit_group;" ::: "memory");

        uint32_t Ab = sbase + (c % STAGES) * (STAGE_FLOATS * 4);
        uint32_t Bb = Ab + OP_FLOATS * 4;

        #pragma unroll
        for (int kk = 0; kk < BK; kk += 8) {
            int ku = kk >> 2;
            uint32_t afr[4][4];
            #pragma unroll
            for (int i = 0; i < 4; i++)
                ldsm4(afr[i], Ab + rowA[i] * (BK * 4)
                               + (((ku + uselA) ^ r7A[i]) << 4));
            uint32_t bfr[2][4];
            #pragma unroll
            for (int jp = 0; jp < 2; jp++)
                ldsm4(bfr[jp], Bb + rowB[jp] * (BK * 4)
                                + (((ku + uselB) ^ r7B[jp]) << 4));
            #pragma unroll
            for (int i = 0; i < 4; i++)
                #pragma unroll
                for (int j = 0; j < 4; j++)
                    mma_tf32(acc[i][j], afr[i],
                             bfr[j >> 1][(j & 1) * 2], bfr[j >> 1][(j & 1) * 2 + 1]);
        }
    }

    // Epilogue: direct tile
    #pragma unroll
    for (int i = 0; i < 4; i++) {
        #pragma unroll
        for (int j = 0; j < 4; j++) {
            int m = m0 + wm + 16 * i + g;
            int n = n0 + wn + 8 * j + 2 * t;
            *(float2*)(Cb + (size_t)m * DDIM + n) =
                make_float2(acc[i][j][0], acc[i][j][1]);
            *(float2*)(Cb + (size_t)(m + 8) * DDIM + n) =
                make_float2(acc[i][j][2], acc[i][j][3]);
        }
    }
    // Mirror for off-diagonal tile pairs
    if (ti != tj) {
        #pragma unroll
        for (int i = 0; i < 4; i++) {
            #pragma unroll
            for (int j = 0; j < 4; j++) {
                int m = m0 + wm + 16 * i + g;
                int n = n0 + wn + 8 * j + 2 * t;
                Cb[(size_t)n * DDIM + m]           = acc[i][j][0];
                Cb[(size_t)(n + 1) * DDIM + m]     = acc[i][j][1];
                Cb[(size_t)n * DDIM + m + 8]       = acc[i][j][2];
                Cb[(size_t)(n + 1) * DDIM + m + 8] = acc[i][j][3];
            }
        }
    }
}

// ---------------------------------------------------------------------------
extern "C" void kernel_launch(void* const* d_in, const int* in_sizes, int n_in,
                              void* d_out, int out_size) {
    const float* x = (const float*)d_in[0];
    float* out = (float*)d_out;

    static int configured = 0;
    if (!configured) {
        cudaFuncSetAttribute(gram_tc_kernel,
                             cudaFuncAttributeMaxDynamicSharedMemorySize, SMEM_BYTES);
        cudaFuncSetAttribute(prep_kernel,
                             cudaFuncAttributeMaxDynamicSharedMemorySize, PREP_SMEM);
        configured = 1;
    }

    prep_kernel<<<dim3(LDIM / 32, BATCH), 256, PREP_SMEM>>>(x);
    gram_tc_kernel<<<BATCH * NPAIRS, 256, SMEM_BYTES>>>(out);
}